// round 7
// baseline (speedup 1.0000x reference)
#include <cuda_runtime.h>
#include <cuda_fp16.h>
#include <math.h>
#include <stdint.h>
#include <mma.h>
using namespace nvcuda;

// ---------------- problem constants ----------------
#define TOK   50176
#define DIM   384
#define QKVD  1152
#define FFN   1536
#define EXPD  768

// ---------------- scratch ----------------
static __device__ float  g_x  [TOK * DIM];     // fp32 residual stream
static __device__ __half g_xh [TOK * DIM];     // fp16 mirror of final residual
static __device__ __half g_y  [TOK * DIM];     // LN outputs (fp16)
static __device__ __half g_o  [TOK * DIM];     // attention out (fp16)
static __device__ float  g_big[TOK * FFN];     // qkv/mid (as half) or expand out (float)
static __device__ __half g_w  [3833856];       // fp16 weights

#define W_QKV 0
#define W_PROJ 884736
#define W_FC1 1179648
#define W_FC2 2359296
#define W_EXP 3538944

// ---------------- helpers ----------------
__device__ __forceinline__ uint32_t smem_u32(const void* p) {
    uint32_t a;
    asm("{ .reg .u64 t; cvta.to.shared.u64 t, %1; cvt.u32.u64 %0, t; }" : "=r"(a) : "l"(p));
    return a;
}
__device__ __forceinline__ void cp16(uint32_t s, const void* g) {
    asm volatile("cp.async.cg.shared.global [%0], [%1], 16;" :: "r"(s), "l"(g) : "memory");
}
#define CP_COMMIT() asm volatile("cp.async.commit_group;" ::: "memory")
#define CP_WAIT(n)  asm volatile("cp.async.wait_group %0;" :: "n"(n) : "memory")

__device__ __forceinline__ int map_row(int ridx, int shifted) {
    int n  = ridx % 49;
    int wi = (ridx / 49) & 63;
    int b  = ridx / (49 * 64);
    int r = n / 7, c = n % 7;
    int wh = wi >> 3, ww = wi & 7;
    int h = wh * 7 + r, w = ww * 7 + c;
    if (shifted) { h = (h + 3) % 56; w = (w + 3) % 56; }
    return b * 3136 + h * 56 + w;
}

// ---------------- fp16 wmma GEMM, cp.async 3-stage, CTA 256x128, warp 64x64, BK=32 ----
// C = A[M,K] @ W[K,Nc] + bias.  8 warps (4 row x 2 col of 64x64 warp tiles).
// epilogue: 0 plain (out_half selects dtype), 1 GELU->half, 2 scatter+residual fp32,
//           3 residual fp32 + half mirror
#define ASTR 40
#define BSTR 136
#define A_STAGE (256 * ASTR)            // 10240 halves
#define B_STAGE (32 * BSTR)             //  4352 halves
#define STG (A_STAGE + B_STAGE)         // 14592 halves = 29184 B / stage
#define OSTR 132

__global__ __launch_bounds__(256, 1)
void gemm_fp16(const __half* __restrict__ A, const __half* __restrict__ W,
               const float* __restrict__ bias, void* __restrict__ Cv,
               __half* __restrict__ mirror,
               int K, int Nc, int epilogue, int shifted, int out_half) {
    extern __shared__ __align__(16) char smraw[];
    __half* smh = (__half*)smraw;
    float*  smf = (float*)smraw;
    int tid = threadIdx.x;
    int wid = tid >> 5;
    int wm = (wid & 3) * 64;       // warp row offset within 256
    int wn = (wid >> 2) * 64;      // warp col offset within 128
    int rowBase = blockIdx.y * 256;
    int colBase = blockIdx.x * 128;
    int nk = K >> 5;

    wmma::fragment<wmma::accumulator, 16, 16, 16, float> acc[4][4];
    #pragma unroll
    for (int i = 0; i < 4; i++)
        #pragma unroll
        for (int j = 0; j < 4; j++) wmma::fill_fragment(acc[i][j], 0.f);

    #define STAGE_LOAD(kt, buf) do {                                              \
        __half* As_ = smh + (buf) * STG;                                          \
        __half* Bs_ = As_ + A_STAGE;                                              \
        uint32_t as_ = smem_u32(As_), bs_ = smem_u32(Bs_);                        \
        int kg_ = (kt) * 32;                                                      \
        _Pragma("unroll")                                                         \
        for (int l = 0; l < 4; l++) {                                             \
            int c = tid + l * 256;                                                \
            int r = c >> 2, q = (c & 3) * 8;                                      \
            cp16(as_ + (uint32_t)(r * ASTR + q) * 2,                              \
                 A + (size_t)(rowBase + r) * K + kg_ + q);                        \
        }                                                                         \
        _Pragma("unroll")                                                         \
        for (int l = 0; l < 2; l++) {                                             \
            int c = tid + l * 256;                                                \
            int kr = c >> 4, nq = (c & 15) * 8;                                   \
            cp16(bs_ + (uint32_t)(kr * BSTR + nq) * 2,                            \
                 W + (size_t)(kg_ + kr) * Nc + colBase + nq);                     \
        }                                                                         \
    } while (0)

    STAGE_LOAD(0, 0); CP_COMMIT();
    STAGE_LOAD(1, 1); CP_COMMIT();

    for (int kt = 0; kt < nk; kt++) {
        if (kt + 2 < nk) { STAGE_LOAD(kt + 2, (kt + 2) % 3); CP_COMMIT(); CP_WAIT(2); }
        else if (kt + 1 < nk) { CP_WAIT(1); }
        else { CP_WAIT(0); }
        __syncthreads();

        const __half* As = smh + (kt % 3) * STG;
        const __half* Bs = As + A_STAGE;
        #pragma unroll
        for (int k16 = 0; k16 < 2; k16++) {
            wmma::fragment<wmma::matrix_a, 16, 16, 16, __half, wmma::row_major> af[4];
            wmma::fragment<wmma::matrix_b, 16, 16, 16, __half, wmma::row_major> bf[4];
            #pragma unroll
            for (int i = 0; i < 4; i++)
                wmma::load_matrix_sync(af[i], As + (wm + i * 16) * ASTR + k16 * 16, ASTR);
            #pragma unroll
            for (int j = 0; j < 4; j++)
                wmma::load_matrix_sync(bf[j], Bs + (k16 * 16) * BSTR + wn + j * 16, BSTR);
            #pragma unroll
            for (int i = 0; i < 4; i++)
                #pragma unroll
                for (int j = 0; j < 4; j++)
                    wmma::mma_sync(acc[i][j], af[i], bf[j], acc[i][j]);
        }
        __syncthreads();
    }

    // epilogue in two 128-row waves through a 128x132 fp32 smem buffer
    #pragma unroll
    for (int h = 0; h < 2; h++) {
        if ((wm >> 7) == h) {
            int wmL = wm & 127;
            #pragma unroll
            for (int i = 0; i < 4; i++)
                #pragma unroll
                for (int j = 0; j < 4; j++)
                    wmma::store_matrix_sync(smf + (wmL + i * 16) * OSTR + wn + j * 16,
                                            acc[i][j], OSTR, wmma::mem_row_major);
        }
        __syncthreads();

        if (epilogue <= 1) {
            if (out_half) {
                __half* C = (__half*)Cv;
                #pragma unroll 4
                for (int e = 0; e < 32; e++) {
                    int idx = tid + e * 256;
                    int r = idx >> 6, c2 = (idx & 63) * 2;
                    int gc = colBase + c2;
                    float v0 = smf[r * OSTR + c2]     + (bias ? bias[gc]     : 0.f);
                    float v1 = smf[r * OSTR + c2 + 1] + (bias ? bias[gc + 1] : 0.f);
                    if (epilogue == 1) {
                        v0 = 0.5f * v0 * (1.f + erff(v0 * 0.7071067811865476f));
                        v1 = 0.5f * v1 * (1.f + erff(v1 * 0.7071067811865476f));
                    }
                    __half2 hh = __floats2half2_rn(v0, v1);
                    *(__half2*)(C + (size_t)(rowBase + h * 128 + r) * Nc + gc) = hh;
                }
            } else {
                float* C = (float*)Cv;
                #pragma unroll 4
                for (int e = 0; e < 64; e++) {
                    int idx = tid + e * 256;
                    int r = idx >> 7, c = idx & 127;
                    int gc = colBase + c;
                    float v = smf[r * OSTR + c] + (bias ? bias[gc] : 0.f);
                    C[(size_t)(rowBase + h * 128 + r) * Nc + gc] = v;
                }
            }
        } else {
            float* C = (float*)Cv;
            #pragma unroll 4
            for (int e = 0; e < 64; e++) {
                int idx = tid + e * 256;
                int r = idx >> 7, c = idx & 127;
                int gr = rowBase + h * 128 + r, gc = colBase + c;
                float v = smf[r * OSTR + c] + bias[gc];
                int orow = (epilogue == 2) ? map_row(gr, shifted) : gr;
                size_t off = (size_t)orow * Nc + gc;
                v += C[off];
                C[off] = v;
                if (epilogue == 3) mirror[off] = __float2half(v);
            }
        }
        __syncthreads();
    }
}

// ---------------- weight fp32 -> fp16 ----------------
__global__ void tohalf_kernel(const float4* __restrict__ in, __half* __restrict__ out, int n4) {
    int i = blockIdx.x * blockDim.x + threadIdx.x;
    if (i < n4) {
        float4 v = in[i];
        __half2* o = (__half2*)(out + i * 4);
        o[0] = __floats2half2_rn(v.x, v.y);
        o[1] = __floats2half2_rn(v.z, v.w);
    }
}

// ---------------- LayerNorm over 384 (half output) ----------------
__device__ __forceinline__ float block_sum(float v, float* sm) {
    #pragma unroll
    for (int o = 16; o; o >>= 1) v += __shfl_xor_sync(0xffffffffu, v, o);
    int w = threadIdx.x >> 5;
    if ((threadIdx.x & 31) == 0) sm[w] = v;
    __syncthreads();
    if (threadIdx.x < 32) {
        float u = (threadIdx.x < (blockDim.x >> 5)) ? sm[threadIdx.x] : 0.f;
        #pragma unroll
        for (int o = 16; o; o >>= 1) u += __shfl_xor_sync(0xffffffffu, u, o);
        if (threadIdx.x == 0) sm[0] = u;
    }
    __syncthreads();
    float r = sm[0];
    __syncthreads();
    return r;
}

__global__ void ln384_kernel(const float* __restrict__ src, __half* __restrict__ dst,
                             const float* __restrict__ g, const float* __restrict__ b,
                             int mode) {
    __shared__ float sm[8];
    int row = blockIdx.x;
    int t = (mode == 0) ? row : map_row(row, mode == 2);
    const float* sp = src + (size_t)t * DIM;
    int tx = threadIdx.x;
    float v0 = sp[tx], v1 = sp[tx + 128], v2 = sp[tx + 256];
    float m = block_sum(v0 + v1 + v2, sm) * (1.f / 384.f);
    float d0 = v0 - m, d1 = v1 - m, d2 = v2 - m;
    float var = block_sum(d0 * d0 + d1 * d1 + d2 * d2, sm) * (1.f / 384.f);
    float inv = rsqrtf(var + 1e-5f);
    __half* dp = dst + (size_t)row * DIM;
    dp[tx]       = __float2half(d0 * inv * g[tx]       + b[tx]);
    dp[tx + 128] = __float2half(d1 * inv * g[tx + 128] + b[tx + 128]);
    dp[tx + 256] = __float2half(d2 * inv * g[tx + 256] + b[tx + 256]);
}

// ---------------- windowed attention: 2 heads per 128-thread block, float4 smem ----------------
__global__ void attn_kernel(const __half* __restrict__ qkv, __half* __restrict__ o,
                            const float* __restrict__ rpb, int shifted) {
    __shared__ float4 ksm[2][49][8];
    __shared__ float4 vsm[2][49][8];
    __shared__ float  ssm[2][49][50];
    int pair = blockIdx.x;
    int win  = pair / 6;
    int hp   = (pair % 6) * 2;
    int sub  = threadIdx.x >> 6;
    int t    = threadIdx.x & 63;
    int head = hp + sub;
    int wi = win & 63;
    int wh = wi >> 3, ww = wi & 7;
    int base = win * 49;

    for (int idx = t; idx < 49 * 8; idx += 64) {
        int j = idx >> 3, d4 = idx & 7;
        size_t ro = (size_t)(base + j) * QKVD + head * 32 + d4 * 4;
        const __half2* kp = (const __half2*)(qkv + ro + 384);
        const __half2* vp = (const __half2*)(qkv + ro + 768);
        float2 k0 = __half22float2(kp[0]), k1 = __half22float2(kp[1]);
        float2 w0 = __half22float2(vp[0]), w1 = __half22float2(vp[1]);
        ksm[sub][j][d4] = make_float4(k0.x, k0.y, k1.x, k1.y);
        vsm[sub][j][d4] = make_float4(w0.x, w0.y, w1.x, w1.y);
    }
    __syncthreads();

    if (t < 49) {
        int i = t, ri = i / 7, ci = i % 7;
        float4 q[8];
        const __half2* qp = (const __half2*)(qkv + (size_t)(base + i) * QKVD + head * 32);
        #pragma unroll
        for (int d4 = 0; d4 < 8; d4++) {
            float2 a = __half22float2(qp[d4 * 2]), b = __half22float2(qp[d4 * 2 + 1]);
            const float sc = 0.17677669529663687f;
            q[d4] = make_float4(a.x * sc, a.y * sc, b.x * sc, b.y * sc);
        }

        int lab_i = 0;
        if (shifted) {
            int hh = wh * 7 + ri, wc = ww * 7 + ci;
            int gh = hh < 49 ? 0 : (hh < 53 ? 1 : 2);
            int gw = wc < 49 ? 0 : (wc < 53 ? 1 : 2);
            lab_i = gh * 3 + gw;
        }
        float mx = -1e30f;
        for (int j = 0; j < 49; j++) {
            float s = 0.f;
            #pragma unroll
            for (int d4 = 0; d4 < 8; d4++) {
                float4 kv = ksm[sub][j][d4];
                s += q[d4].x * kv.x + q[d4].y * kv.y + q[d4].z * kv.z + q[d4].w * kv.w;
            }
            int rj = j / 7, cj = j % 7;
            int rpi = (ri - rj + 6) * 13 + (ci - cj + 6);
            s += rpb[rpi * 12 + head];
            if (shifted) {
                int hh = wh * 7 + rj, wc = ww * 7 + cj;
                int gh = hh < 49 ? 0 : (hh < 53 ? 1 : 2);
                int gw = wc < 49 ? 0 : (wc < 53 ? 1 : 2);
                if (gh * 3 + gw != lab_i) s -= 100.0f;
            }
            ssm[sub][i][j] = s;
            mx = fmaxf(mx, s);
        }
        float sum = 0.f;
        for (int j = 0; j < 49; j++) {
            float e = expf(ssm[sub][i][j] - mx);
            ssm[sub][i][j] = e;
            sum += e;
        }
        float inv = 1.0f / sum;
        float4 accv[8];
        #pragma unroll
        for (int d4 = 0; d4 < 8; d4++) accv[d4] = make_float4(0.f, 0.f, 0.f, 0.f);
        for (int j = 0; j < 49; j++) {
            float p = ssm[sub][i][j] * inv;
            #pragma unroll
            for (int d4 = 0; d4 < 8; d4++) {
                float4 vv = vsm[sub][j][d4];
                accv[d4].x += p * vv.x; accv[d4].y += p * vv.y;
                accv[d4].z += p * vv.z; accv[d4].w += p * vv.w;
            }
        }
        __half2* op = (__half2*)(o + (size_t)(base + i) * DIM + head * 32);
        #pragma unroll
        for (int d4 = 0; d4 < 8; d4++) {
            op[d4 * 2]     = __floats2half2_rn(accv[d4].x, accv[d4].y);
            op[d4 * 2 + 1] = __floats2half2_rn(accv[d4].z, accv[d4].w);
        }
    }
}

// ---------------- PatchExpand pixel-shuffle + LN over 192 ----------------
__global__ void expand_ln_kernel(const float* __restrict__ e, float* __restrict__ out,
                                 const float* __restrict__ g, const float* __restrict__ b) {
    __shared__ float sm[8];
    int tt = blockIdx.x;
    int bb = tt / 12544;
    int rem = tt % 12544;
    int oh = rem / 112, ow = rem % 112;
    int h = oh >> 1, p = oh & 1, w = ow >> 1, q = ow & 1;
    int erow = bb * 3136 + h * 56 + w;
    const float* sp = e + (size_t)erow * EXPD + (p * 2 + q) * 192;
    int tx = threadIdx.x;
    float v0 = sp[tx], v1 = sp[tx + 64], v2 = sp[tx + 128];
    float m = block_sum(v0 + v1 + v2, sm) * (1.f / 192.f);
    float d0 = v0 - m, d1 = v1 - m, d2 = v2 - m;
    float var = block_sum(d0 * d0 + d1 * d1 + d2 * d2, sm) * (1.f / 192.f);
    float inv = rsqrtf(var + 1e-5f);
    float* dp = out + (size_t)tt * 192;
    dp[tx]       = d0 * inv * g[tx]       + b[tx];
    dp[tx + 64]  = d1 * inv * g[tx + 64]  + b[tx + 64];
    dp[tx + 128] = d2 * inv * g[tx + 128] + b[tx + 128];
}

__global__ void copy_kernel(float4* __restrict__ dst, const float4* __restrict__ src, int n) {
    int i = blockIdx.x * blockDim.x + threadIdx.x;
    if (i < n) dst[i] = src[i];
}

// ---------------- host orchestration ----------------
extern "C" void kernel_launch(void* const* d_in, const int* in_sizes, int n_in,
                              void* d_out, int out_size) {
    const float* x    = (const float*)d_in[0];
    const float* n1g  = (const float*)d_in[1];
    const float* n1b  = (const float*)d_in[2];
    const float* qkvw = (const float*)d_in[3];
    const float* qkvb = (const float*)d_in[4];
    const float* rpb  = (const float*)d_in[5];
    const float* pw   = (const float*)d_in[6];
    const float* pb   = (const float*)d_in[7];
    const float* n2g  = (const float*)d_in[8];
    const float* n2b  = (const float*)d_in[9];
    const float* f1w  = (const float*)d_in[10];
    const float* f1b  = (const float*)d_in[11];
    const float* f2w  = (const float*)d_in[12];
    const float* f2b  = (const float*)d_in[13];
    const float* ew   = (const float*)d_in[14];
    const float* eg   = (const float*)d_in[15];
    const float* ebv  = (const float*)d_in[16];

    float *xb, *bigb;
    __half *xh, *yh, *oh, *wh;
    cudaGetSymbolAddress((void**)&xb,   g_x);
    cudaGetSymbolAddress((void**)&xh,   g_xh);
    cudaGetSymbolAddress((void**)&yh,   g_y);
    cudaGetSymbolAddress((void**)&oh,   g_o);
    cudaGetSymbolAddress((void**)&bigb, g_big);
    cudaGetSymbolAddress((void**)&wh,   g_w);

    static int smem_set = 0;
    const int GEMM_SMEM = 3 * STG * sizeof(__half);   // 87552 B
    if (!smem_set) {
        cudaFuncSetAttribute(gemm_fp16,
                             cudaFuncAttributeMaxDynamicSharedMemorySize, GEMM_SMEM);
        smem_set = 1;
    }

    // convert all weights to fp16 once
    tohalf_kernel<<<(884736/4 + 255)/256, 256>>>((const float4*)qkvw, wh + W_QKV, 884736/4);
    tohalf_kernel<<<(294912/4 + 255)/256, 256>>>((const float4*)pw,   wh + W_PROJ, 294912/4);
    tohalf_kernel<<<(1179648/4 + 255)/256, 256>>>((const float4*)f1w, wh + W_FC1, 1179648/4);
    tohalf_kernel<<<(1179648/4 + 255)/256, 256>>>((const float4*)f2w, wh + W_FC2, 1179648/4);
    tohalf_kernel<<<(294912/4 + 255)/256, 256>>>((const float4*)ew,   wh + W_EXP, 294912/4);

    copy_kernel<<<18816, 256>>>((float4*)xb, (const float4*)x, TOK * DIM / 4);

    const int MB = TOK / 256;   // 196 row tiles
    for (int i = 0; i < 2; i++) {
        int sh = i;
        ln384_kernel<<<TOK, 128>>>(xb, yh, n1g + i * DIM, n1b + i * DIM, sh ? 2 : 1);
        gemm_fp16<<<dim3(QKVD / 128, MB), 256, GEMM_SMEM>>>(
            yh, wh + W_QKV + (size_t)i * DIM * QKVD, qkvb + i * QKVD,
            bigb, nullptr, DIM, QKVD, 0, 0, 1);
        attn_kernel<<<1024 * 6, 128>>>((const __half*)bigb, oh, rpb + i * 169 * 12, sh);
        gemm_fp16<<<dim3(DIM / 128, MB), 256, GEMM_SMEM>>>(
            oh, wh + W_PROJ + (size_t)i * DIM * DIM, pb + i * DIM,
            xb, nullptr, DIM, DIM, 2, sh, 0);
        ln384_kernel<<<TOK, 128>>>(xb, yh, n2g + i * DIM, n2b + i * DIM, 0);
        gemm_fp16<<<dim3(FFN / 128, MB), 256, GEMM_SMEM>>>(
            yh, wh + W_FC1 + (size_t)i * DIM * FFN, f1b + i * FFN,
            bigb, nullptr, DIM, FFN, 1, 0, 1);
        gemm_fp16<<<dim3(DIM / 128, MB), 256, GEMM_SMEM>>>(
            (const __half*)bigb, wh + W_FC2 + (size_t)i * FFN * DIM, f2b + i * DIM,
            xb, xh, FFN, DIM, 3, 0, 0);
    }

    // expand GEMM reads fp16 mirror of final residual, writes fp32 for the LN
    gemm_fp16<<<dim3(EXPD / 128, MB), 256, GEMM_SMEM>>>(
        xh, wh + W_EXP, nullptr, bigb, nullptr, DIM, EXPD, 0, 0, 0);
    expand_ln_kernel<<<TOK * 4, 64>>>(bigb, (float*)d_out, eg, ebv);
}

// round 8
// speedup vs baseline: 1.3624x; 1.3624x over previous
#include <cuda_runtime.h>
#include <cuda_fp16.h>
#include <math.h>
#include <stdint.h>
#include <mma.h>
using namespace nvcuda;

// ---------------- problem constants ----------------
#define TOK   50176
#define DIM   384
#define QKVD  1152
#define FFN   1536
#define EXPD  768

// ---------------- scratch ----------------
static __device__ float  g_x  [TOK * DIM];     // fp32 residual stream
static __device__ __half g_xh [TOK * DIM];     // fp16 mirror of final residual
static __device__ __half g_y  [TOK * DIM];     // LN outputs (fp16)
static __device__ __half g_o  [TOK * DIM];     // attention out (fp16)
static __device__ float  g_big[TOK * FFN];     // qkv/mid (as half) or expand out (float)
static __device__ __half g_w  [3833856];       // fp16 weights

#define W_QKV 0
#define W_PROJ 884736
#define W_FC1 1179648
#define W_FC2 2359296
#define W_EXP 3538944

// ---------------- helpers ----------------
__device__ __forceinline__ uint32_t smem_u32(const void* p) {
    uint32_t a;
    asm("{ .reg .u64 t; cvta.to.shared.u64 t, %1; cvt.u32.u64 %0, t; }" : "=r"(a) : "l"(p));
    return a;
}
__device__ __forceinline__ void cp16(uint32_t s, const void* g) {
    asm volatile("cp.async.cg.shared.global [%0], [%1], 16;" :: "r"(s), "l"(g) : "memory");
}
#define CP_COMMIT() asm volatile("cp.async.commit_group;" ::: "memory")
#define CP_WAIT(n)  asm volatile("cp.async.wait_group %0;" :: "n"(n) : "memory")

__device__ __forceinline__ int map_row(int ridx, int shifted) {
    int n  = ridx % 49;
    int wi = (ridx / 49) & 63;
    int b  = ridx / (49 * 64);
    int r = n / 7, c = n % 7;
    int wh = wi >> 3, ww = wi & 7;
    int h = wh * 7 + r, w = ww * 7 + c;
    if (shifted) { h = (h + 3) % 56; w = (w + 3) % 56; }
    return b * 3136 + h * 56 + w;
}

// ---------------- fp16 wmma GEMM: CTA 128x128, 4 warps of 64x64, BK=64, 3-stage ----
// C = A[M,K] @ W[K,Nc] + bias.
// epilogue: 0 plain (out_half selects dtype), 1 GELU->half,
//           2 scatter + resid add (reads resid, writes C fp32),
//           3 resid add (resid==C) + half mirror
#define ASTR 72
#define BSTR 136
#define A_STAGE (128 * ASTR)            // 9216 halves
#define B_STAGE (64 * BSTR)             // 8704 halves
#define STG (A_STAGE + B_STAGE)         // 17920 halves = 35840 B / stage
#define OSTR 132

__global__ __launch_bounds__(128, 2)
void gemm_fp16(const __half* __restrict__ A, const __half* __restrict__ W,
               const float* __restrict__ bias, void* __restrict__ Cv,
               __half* __restrict__ mirror, const float* __restrict__ resid,
               int K, int Nc, int epilogue, int shifted, int out_half) {
    extern __shared__ __align__(16) char smraw[];
    __half* smh = (__half*)smraw;
    float*  smf = (float*)smraw;
    int tid = threadIdx.x;
    int wid = tid >> 5;
    int wm = (wid & 1) * 64;       // warp row offset
    int wn = (wid >> 1) * 64;      // warp col offset
    int rowBase = blockIdx.y * 128;
    int colBase = blockIdx.x * 128;
    int nk = K >> 6;

    wmma::fragment<wmma::accumulator, 16, 16, 16, float> acc[4][4];
    #pragma unroll
    for (int i = 0; i < 4; i++)
        #pragma unroll
        for (int j = 0; j < 4; j++) wmma::fill_fragment(acc[i][j], 0.f);

    #define STAGE_LOAD(kt, buf) do {                                              \
        __half* As_ = smh + (buf) * STG;                                          \
        __half* Bs_ = As_ + A_STAGE;                                              \
        uint32_t as_ = smem_u32(As_), bs_ = smem_u32(Bs_);                        \
        int kg_ = (kt) * 64;                                                      \
        _Pragma("unroll")                                                         \
        for (int l = 0; l < 8; l++) {                                             \
            int c = tid + l * 128;                                                \
            int r = c >> 3, q = (c & 7) * 8;                                      \
            cp16(as_ + (uint32_t)(r * ASTR + q) * 2,                              \
                 A + (size_t)(rowBase + r) * K + kg_ + q);                        \
            int kr = c >> 4, nq = (c & 15) * 8;                                   \
            cp16(bs_ + (uint32_t)(kr * BSTR + nq) * 2,                            \
                 W + (size_t)(kg_ + kr) * Nc + colBase + nq);                     \
        }                                                                         \
    } while (0)

    STAGE_LOAD(0, 0); CP_COMMIT();
    STAGE_LOAD(1, 1); CP_COMMIT();

    for (int kt = 0; kt < nk; kt++) {
        if (kt + 2 < nk) { STAGE_LOAD(kt + 2, (kt + 2) % 3); CP_COMMIT(); CP_WAIT(2); }
        else if (kt + 1 < nk) { CP_WAIT(1); }
        else { CP_WAIT(0); }
        __syncthreads();

        const __half* As = smh + (kt % 3) * STG;
        const __half* Bs = As + A_STAGE;
        #pragma unroll
        for (int k16 = 0; k16 < 4; k16++) {
            wmma::fragment<wmma::matrix_a, 16, 16, 16, __half, wmma::row_major> af[4];
            wmma::fragment<wmma::matrix_b, 16, 16, 16, __half, wmma::row_major> bf[4];
            #pragma unroll
            for (int i = 0; i < 4; i++)
                wmma::load_matrix_sync(af[i], As + (wm + i * 16) * ASTR + k16 * 16, ASTR);
            #pragma unroll
            for (int j = 0; j < 4; j++)
                wmma::load_matrix_sync(bf[j], Bs + (k16 * 16) * BSTR + wn + j * 16, BSTR);
            #pragma unroll
            for (int i = 0; i < 4; i++)
                #pragma unroll
                for (int j = 0; j < 4; j++)
                    wmma::mma_sync(acc[i][j], af[i], bf[j], acc[i][j]);
        }
        __syncthreads();
    }

    // stage accumulators to smem as fp32 (reuses pipeline buffers)
    #pragma unroll
    for (int i = 0; i < 4; i++)
        #pragma unroll
        for (int j = 0; j < 4; j++)
            wmma::store_matrix_sync(smf + (wm + i * 16) * OSTR + wn + j * 16,
                                    acc[i][j], OSTR, wmma::mem_row_major);
    __syncthreads();

    if (epilogue <= 1) {
        if (out_half) {
            __half* C = (__half*)Cv;
            #pragma unroll 4
            for (int e = 0; e < 64; e++) {
                int idx = tid + e * 128;
                int r = idx >> 6, c2 = (idx & 63) * 2;
                int gc = colBase + c2;
                float v0 = smf[r * OSTR + c2]     + (bias ? bias[gc]     : 0.f);
                float v1 = smf[r * OSTR + c2 + 1] + (bias ? bias[gc + 1] : 0.f);
                if (epilogue == 1) {
                    v0 = 0.5f * v0 * (1.f + erff(v0 * 0.7071067811865476f));
                    v1 = 0.5f * v1 * (1.f + erff(v1 * 0.7071067811865476f));
                }
                __half2 hh = __floats2half2_rn(v0, v1);
                *(__half2*)(C + (size_t)(rowBase + r) * Nc + gc) = hh;
            }
        } else {
            float* C = (float*)Cv;
            #pragma unroll 4
            for (int e = 0; e < 128; e++) {
                int r = e, c = tid;
                int gc = colBase + c;
                float v = smf[r * OSTR + c] + (bias ? bias[gc] : 0.f);
                C[(size_t)(rowBase + r) * Nc + gc] = v;
            }
        }
    } else {
        float* C = (float*)Cv;
        #pragma unroll 4
        for (int e = 0; e < 128; e++) {
            int r = e, c = tid;
            int gr = rowBase + r, gc = colBase + c;
            float v = smf[r * OSTR + c] + bias[gc];
            int orow = (epilogue == 2) ? map_row(gr, shifted) : gr;
            size_t off = (size_t)orow * Nc + gc;
            v += resid[off];
            C[off] = v;
            if (epilogue == 3) mirror[off] = __float2half(v);
        }
    }
}

// ---------------- weight fp32 -> fp16 ----------------
__global__ void tohalf_kernel(const float4* __restrict__ in, __half* __restrict__ out, int n4) {
    int i = blockIdx.x * blockDim.x + threadIdx.x;
    if (i < n4) {
        float4 v = in[i];
        __half2* o = (__half2*)(out + i * 4);
        o[0] = __floats2half2_rn(v.x, v.y);
        o[1] = __floats2half2_rn(v.z, v.w);
    }
}

// ---------------- LayerNorm over 384 (half output) ----------------
__device__ __forceinline__ float block_sum(float v, float* sm) {
    #pragma unroll
    for (int o = 16; o; o >>= 1) v += __shfl_xor_sync(0xffffffffu, v, o);
    int w = threadIdx.x >> 5;
    if ((threadIdx.x & 31) == 0) sm[w] = v;
    __syncthreads();
    if (threadIdx.x < 32) {
        float u = (threadIdx.x < (blockDim.x >> 5)) ? sm[threadIdx.x] : 0.f;
        #pragma unroll
        for (int o = 16; o; o >>= 1) u += __shfl_xor_sync(0xffffffffu, u, o);
        if (threadIdx.x == 0) sm[0] = u;
    }
    __syncthreads();
    float r = sm[0];
    __syncthreads();
    return r;
}

__global__ void ln384_kernel(const float* __restrict__ src, __half* __restrict__ dst,
                             const float* __restrict__ g, const float* __restrict__ b,
                             int mode) {
    __shared__ float sm[8];
    int row = blockIdx.x;
    int t = (mode == 0) ? row : map_row(row, mode == 2);
    const float* sp = src + (size_t)t * DIM;
    int tx = threadIdx.x;
    float v0 = sp[tx], v1 = sp[tx + 128], v2 = sp[tx + 256];
    float m = block_sum(v0 + v1 + v2, sm) * (1.f / 384.f);
    float d0 = v0 - m, d1 = v1 - m, d2 = v2 - m;
    float var = block_sum(d0 * d0 + d1 * d1 + d2 * d2, sm) * (1.f / 384.f);
    float inv = rsqrtf(var + 1e-5f);
    __half* dp = dst + (size_t)row * DIM;
    dp[tx]       = __float2half(d0 * inv * g[tx]       + b[tx]);
    dp[tx + 128] = __float2half(d1 * inv * g[tx + 128] + b[tx + 128]);
    dp[tx + 256] = __float2half(d2 * inv * g[tx + 256] + b[tx + 256]);
}

// ---------------- windowed attention: 2 heads per 128-thread block, float4 smem ----------------
__global__ void attn_kernel(const __half* __restrict__ qkv, __half* __restrict__ o,
                            const float* __restrict__ rpb, int shifted) {
    __shared__ float4 ksm[2][49][8];
    __shared__ float4 vsm[2][49][8];
    __shared__ float  ssm[2][49][50];
    int pair = blockIdx.x;
    int win  = pair / 6;
    int hp   = (pair % 6) * 2;
    int sub  = threadIdx.x >> 6;
    int t    = threadIdx.x & 63;
    int head = hp + sub;
    int wi = win & 63;
    int wh = wi >> 3, ww = wi & 7;
    int base = win * 49;

    for (int idx = t; idx < 49 * 8; idx += 64) {
        int j = idx >> 3, d4 = idx & 7;
        size_t ro = (size_t)(base + j) * QKVD + head * 32 + d4 * 4;
        const __half2* kp = (const __half2*)(qkv + ro + 384);
        const __half2* vp = (const __half2*)(qkv + ro + 768);
        float2 k0 = __half22float2(kp[0]), k1 = __half22float2(kp[1]);
        float2 w0 = __half22float2(vp[0]), w1 = __half22float2(vp[1]);
        ksm[sub][j][d4] = make_float4(k0.x, k0.y, k1.x, k1.y);
        vsm[sub][j][d4] = make_float4(w0.x, w0.y, w1.x, w1.y);
    }
    __syncthreads();

    if (t < 49) {
        int i = t, ri = i / 7, ci = i % 7;
        float4 q[8];
        const __half2* qp = (const __half2*)(qkv + (size_t)(base + i) * QKVD + head * 32);
        #pragma unroll
        for (int d4 = 0; d4 < 8; d4++) {
            float2 a = __half22float2(qp[d4 * 2]), b = __half22float2(qp[d4 * 2 + 1]);
            const float sc = 0.17677669529663687f;
            q[d4] = make_float4(a.x * sc, a.y * sc, b.x * sc, b.y * sc);
        }

        int lab_i = 0;
        if (shifted) {
            int hh = wh * 7 + ri, wc = ww * 7 + ci;
            int gh = hh < 49 ? 0 : (hh < 53 ? 1 : 2);
            int gw = wc < 49 ? 0 : (wc < 53 ? 1 : 2);
            lab_i = gh * 3 + gw;
        }
        float mx = -1e30f;
        for (int j = 0; j < 49; j++) {
            float s = 0.f;
            #pragma unroll
            for (int d4 = 0; d4 < 8; d4++) {
                float4 kv = ksm[sub][j][d4];
                s += q[d4].x * kv.x + q[d4].y * kv.y + q[d4].z * kv.z + q[d4].w * kv.w;
            }
            int rj = j / 7, cj = j % 7;
            int rpi = (ri - rj + 6) * 13 + (ci - cj + 6);
            s += rpb[rpi * 12 + head];
            if (shifted) {
                int hh = wh * 7 + rj, wc = ww * 7 + cj;
                int gh = hh < 49 ? 0 : (hh < 53 ? 1 : 2);
                int gw = wc < 49 ? 0 : (wc < 53 ? 1 : 2);
                if (gh * 3 + gw != lab_i) s -= 100.0f;
            }
            ssm[sub][i][j] = s;
            mx = fmaxf(mx, s);
        }
        float sum = 0.f;
        for (int j = 0; j < 49; j++) {
            float e = expf(ssm[sub][i][j] - mx);
            ssm[sub][i][j] = e;
            sum += e;
        }
        float inv = 1.0f / sum;
        float4 accv[8];
        #pragma unroll
        for (int d4 = 0; d4 < 8; d4++) accv[d4] = make_float4(0.f, 0.f, 0.f, 0.f);
        for (int j = 0; j < 49; j++) {
            float p = ssm[sub][i][j] * inv;
            #pragma unroll
            for (int d4 = 0; d4 < 8; d4++) {
                float4 vv = vsm[sub][j][d4];
                accv[d4].x += p * vv.x; accv[d4].y += p * vv.y;
                accv[d4].z += p * vv.z; accv[d4].w += p * vv.w;
            }
        }
        __half2* op = (__half2*)(o + (size_t)(base + i) * DIM + head * 32);
        #pragma unroll
        for (int d4 = 0; d4 < 8; d4++) {
            op[d4 * 2]     = __floats2half2_rn(accv[d4].x, accv[d4].y);
            op[d4 * 2 + 1] = __floats2half2_rn(accv[d4].z, accv[d4].w);
        }
    }
}

// ---------------- PatchExpand pixel-shuffle + LN over 192 ----------------
__global__ void expand_ln_kernel(const float* __restrict__ e, float* __restrict__ out,
                                 const float* __restrict__ g, const float* __restrict__ b) {
    __shared__ float sm[8];
    int tt = blockIdx.x;
    int bb = tt / 12544;
    int rem = tt % 12544;
    int oh = rem / 112, ow = rem % 112;
    int h = oh >> 1, p = oh & 1, w = ow >> 1, q = ow & 1;
    int erow = bb * 3136 + h * 56 + w;
    const float* sp = e + (size_t)erow * EXPD + (p * 2 + q) * 192;
    int tx = threadIdx.x;
    float v0 = sp[tx], v1 = sp[tx + 64], v2 = sp[tx + 128];
    float m = block_sum(v0 + v1 + v2, sm) * (1.f / 192.f);
    float d0 = v0 - m, d1 = v1 - m, d2 = v2 - m;
    float var = block_sum(d0 * d0 + d1 * d1 + d2 * d2, sm) * (1.f / 192.f);
    float inv = rsqrtf(var + 1e-5f);
    float* dp = out + (size_t)tt * 192;
    dp[tx]       = d0 * inv * g[tx]       + b[tx];
    dp[tx + 64]  = d1 * inv * g[tx + 64]  + b[tx + 64];
    dp[tx + 128] = d2 * inv * g[tx + 128] + b[tx + 128];
}

// ---------------- host orchestration ----------------
extern "C" void kernel_launch(void* const* d_in, const int* in_sizes, int n_in,
                              void* d_out, int out_size) {
    const float* x    = (const float*)d_in[0];
    const float* n1g  = (const float*)d_in[1];
    const float* n1b  = (const float*)d_in[2];
    const float* qkvw = (const float*)d_in[3];
    const float* qkvb = (const float*)d_in[4];
    const float* rpb  = (const float*)d_in[5];
    const float* pw   = (const float*)d_in[6];
    const float* pb   = (const float*)d_in[7];
    const float* n2g  = (const float*)d_in[8];
    const float* n2b  = (const float*)d_in[9];
    const float* f1w  = (const float*)d_in[10];
    const float* f1b  = (const float*)d_in[11];
    const float* f2w  = (const float*)d_in[12];
    const float* f2b  = (const float*)d_in[13];
    const float* ew   = (const float*)d_in[14];
    const float* eg   = (const float*)d_in[15];
    const float* ebv  = (const float*)d_in[16];

    float *xb, *bigb;
    __half *xh, *yh, *oh, *wh;
    cudaGetSymbolAddress((void**)&xb,   g_x);
    cudaGetSymbolAddress((void**)&xh,   g_xh);
    cudaGetSymbolAddress((void**)&yh,   g_y);
    cudaGetSymbolAddress((void**)&oh,   g_o);
    cudaGetSymbolAddress((void**)&bigb, g_big);
    cudaGetSymbolAddress((void**)&wh,   g_w);

    static int smem_set = 0;
    const int GEMM_SMEM = 3 * STG * sizeof(__half);   // 107520 B
    if (!smem_set) {
        cudaFuncSetAttribute(gemm_fp16,
                             cudaFuncAttributeMaxDynamicSharedMemorySize, GEMM_SMEM);
        smem_set = 1;
    }

    // convert all weights to fp16 once
    tohalf_kernel<<<(884736/4 + 255)/256, 256>>>((const float4*)qkvw, wh + W_QKV, 884736/4);
    tohalf_kernel<<<(294912/4 + 255)/256, 256>>>((const float4*)pw,   wh + W_PROJ, 294912/4);
    tohalf_kernel<<<(1179648/4 + 255)/256, 256>>>((const float4*)f1w, wh + W_FC1, 1179648/4);
    tohalf_kernel<<<(1179648/4 + 255)/256, 256>>>((const float4*)f2w, wh + W_FC2, 1179648/4);
    tohalf_kernel<<<(294912/4 + 255)/256, 256>>>((const float4*)ew,   wh + W_EXP, 294912/4);

    const int MB = TOK / 128;   // 392 row tiles
    for (int i = 0; i < 2; i++) {
        int sh = i;
        // LN1 reads the live residual: input x for block 0, xb afterwards
        const float* res = (i == 0) ? x : xb;
        ln384_kernel<<<TOK, 128>>>(res, yh, n1g + i * DIM, n1b + i * DIM, sh ? 2 : 1);
        gemm_fp16<<<dim3(QKVD / 128, MB), 128, GEMM_SMEM>>>(
            yh, wh + W_QKV + (size_t)i * DIM * QKVD, qkvb + i * QKVD,
            bigb, nullptr, nullptr, DIM, QKVD, 0, 0, 1);
        attn_kernel<<<1024 * 6, 128>>>((const __half*)bigb, oh, rpb + i * 169 * 12, sh);
        // proj: adds residual from res (x input for block 0), writes xb
        gemm_fp16<<<dim3(DIM / 128, MB), 128, GEMM_SMEM>>>(
            oh, wh + W_PROJ + (size_t)i * DIM * DIM, pb + i * DIM,
            xb, nullptr, res, DIM, DIM, 2, sh, 0);
        ln384_kernel<<<TOK, 128>>>(xb, yh, n2g + i * DIM, n2b + i * DIM, 0);
        gemm_fp16<<<dim3(FFN / 128, MB), 128, GEMM_SMEM>>>(
            yh, wh + W_FC1 + (size_t)i * DIM * FFN, f1b + i * FFN,
            bigb, nullptr, nullptr, DIM, FFN, 1, 0, 1);
        gemm_fp16<<<dim3(DIM / 128, MB), 128, GEMM_SMEM>>>(
            (const __half*)bigb, wh + W_FC2 + (size_t)i * FFN * DIM, f2b + i * DIM,
            xb, xh, xb, FFN, DIM, 3, 0, 0);
    }

    // expand GEMM reads fp16 mirror of final residual, writes fp32 for the LN
    gemm_fp16<<<dim3(EXPD / 128, MB), 128, GEMM_SMEM>>>(
        xh, wh + W_EXP, nullptr, bigb, nullptr, nullptr, DIM, EXPD, 0, 0, 0);
    expand_ln_kernel<<<TOK * 4, 64>>>(bigb, (float*)d_out, eg, ebv);
}

// round 9
// speedup vs baseline: 1.4856x; 1.0904x over previous
#include <cuda_runtime.h>
#include <cuda_fp16.h>
#include <math.h>
#include <stdint.h>
#include <mma.h>
using namespace nvcuda;

// ---------------- problem constants ----------------
#define TOK   50176
#define DIM   384
#define QKVD  1152
#define FFN   1536
#define EXPD  768

// ---------------- scratch ----------------
static __device__ float  g_x  [TOK * DIM];     // fp32 residual stream
static __device__ __half g_xh [TOK * DIM];     // fp16 mirror of final residual
static __device__ __half g_y  [TOK * DIM];     // LN outputs (fp16)
static __device__ __half g_o  [TOK * DIM];     // attention out (fp16)
static __device__ float  g_big[TOK * FFN];     // qkv/mid (as half) or expand out (float)
static __device__ __half g_w  [3833856];       // fp16 weights

#define W_QKV 0
#define W_PROJ 884736
#define W_FC1 1179648
#define W_FC2 2359296
#define W_EXP 3538944

// ---------------- helpers ----------------
__device__ __forceinline__ uint32_t smem_u32(const void* p) {
    uint32_t a;
    asm("{ .reg .u64 t; cvta.to.shared.u64 t, %1; cvt.u32.u64 %0, t; }" : "=r"(a) : "l"(p));
    return a;
}
__device__ __forceinline__ void cp16(uint32_t s, const void* g) {
    asm volatile("cp.async.cg.shared.global [%0], [%1], 16;" :: "r"(s), "l"(g) : "memory");
}
#define CP_COMMIT() asm volatile("cp.async.commit_group;" ::: "memory")
#define CP_WAIT(n)  asm volatile("cp.async.wait_group %0;" :: "n"(n) : "memory")

__device__ __forceinline__ int map_row(int ridx, int shifted) {
    int n  = ridx % 49;
    int wi = (ridx / 49) & 63;
    int b  = ridx / (49 * 64);
    int r = n / 7, c = n % 7;
    int wh = wi >> 3, ww = wi & 7;
    int h = wh * 7 + r, w = ww * 7 + c;
    if (shifted) { h = (h + 3) % 56; w = (w + 3) % 56; }
    return b * 3136 + h * 56 + w;
}

__device__ __forceinline__ float warp_sum(float v) {
    #pragma unroll
    for (int o = 16; o; o >>= 1) v += __shfl_xor_sync(0xffffffffu, v, o);
    return v;
}

// ---------------- fp16 wmma GEMM: CTA 128x128, 4 warps of 64x64, BK=64, 3-stage ----
#define ASTR 72
#define BSTR 136
#define A_STAGE (128 * ASTR)
#define B_STAGE (64 * BSTR)
#define STG (A_STAGE + B_STAGE)         // 17920 halves = 35840 B / stage
#define OSTR 132

__global__ __launch_bounds__(128, 2)
void gemm_fp16(const __half* __restrict__ A, const __half* __restrict__ W,
               const float* __restrict__ bias, void* __restrict__ Cv,
               __half* __restrict__ mirror, const float* __restrict__ resid,
               int K, int Nc, int epilogue, int shifted, int out_half) {
    extern __shared__ __align__(16) char smraw[];
    __half* smh = (__half*)smraw;
    float*  smf = (float*)smraw;
    int tid = threadIdx.x;
    int wid = tid >> 5;
    int wm = (wid & 1) * 64;
    int wn = (wid >> 1) * 64;
    int rowBase = blockIdx.y * 128;
    int colBase = blockIdx.x * 128;
    int nk = K >> 6;

    wmma::fragment<wmma::accumulator, 16, 16, 16, float> acc[4][4];
    #pragma unroll
    for (int i = 0; i < 4; i++)
        #pragma unroll
        for (int j = 0; j < 4; j++) wmma::fill_fragment(acc[i][j], 0.f);

    #define STAGE_LOAD(kt, buf) do {                                              \
        __half* As_ = smh + (buf) * STG;                                          \
        __half* Bs_ = As_ + A_STAGE;                                              \
        uint32_t as_ = smem_u32(As_), bs_ = smem_u32(Bs_);                        \
        int kg_ = (kt) * 64;                                                      \
        _Pragma("unroll")                                                         \
        for (int l = 0; l < 8; l++) {                                             \
            int c = tid + l * 128;                                                \
            int r = c >> 3, q = (c & 7) * 8;                                      \
            cp16(as_ + (uint32_t)(r * ASTR + q) * 2,                              \
                 A + (size_t)(rowBase + r) * K + kg_ + q);                        \
            int kr = c >> 4, nq = (c & 15) * 8;                                   \
            cp16(bs_ + (uint32_t)(kr * BSTR + nq) * 2,                            \
                 W + (size_t)(kg_ + kr) * Nc + colBase + nq);                     \
        }                                                                         \
    } while (0)

    STAGE_LOAD(0, 0); CP_COMMIT();
    STAGE_LOAD(1, 1); CP_COMMIT();

    for (int kt = 0; kt < nk; kt++) {
        if (kt + 2 < nk) { STAGE_LOAD(kt + 2, (kt + 2) % 3); CP_COMMIT(); CP_WAIT(2); }
        else if (kt + 1 < nk) { CP_WAIT(1); }
        else { CP_WAIT(0); }
        __syncthreads();

        const __half* As = smh + (kt % 3) * STG;
        const __half* Bs = As + A_STAGE;
        #pragma unroll
        for (int k16 = 0; k16 < 4; k16++) {
            wmma::fragment<wmma::matrix_a, 16, 16, 16, __half, wmma::row_major> af[4];
            wmma::fragment<wmma::matrix_b, 16, 16, 16, __half, wmma::row_major> bf[4];
            #pragma unroll
            for (int i = 0; i < 4; i++)
                wmma::load_matrix_sync(af[i], As + (wm + i * 16) * ASTR + k16 * 16, ASTR);
            #pragma unroll
            for (int j = 0; j < 4; j++)
                wmma::load_matrix_sync(bf[j], Bs + (k16 * 16) * BSTR + wn + j * 16, BSTR);
            #pragma unroll
            for (int i = 0; i < 4; i++)
                #pragma unroll
                for (int j = 0; j < 4; j++)
                    wmma::mma_sync(acc[i][j], af[i], bf[j], acc[i][j]);
        }
        __syncthreads();
    }

    #pragma unroll
    for (int i = 0; i < 4; i++)
        #pragma unroll
        for (int j = 0; j < 4; j++)
            wmma::store_matrix_sync(smf + (wm + i * 16) * OSTR + wn + j * 16,
                                    acc[i][j], OSTR, wmma::mem_row_major);
    __syncthreads();

    if (epilogue <= 1) {
        if (out_half) {
            __half* C = (__half*)Cv;
            #pragma unroll 4
            for (int e = 0; e < 64; e++) {
                int idx = tid + e * 128;
                int r = idx >> 6, c2 = (idx & 63) * 2;
                int gc = colBase + c2;
                float v0 = smf[r * OSTR + c2]     + (bias ? bias[gc]     : 0.f);
                float v1 = smf[r * OSTR + c2 + 1] + (bias ? bias[gc + 1] : 0.f);
                if (epilogue == 1) {
                    v0 = 0.5f * v0 * (1.f + erff(v0 * 0.7071067811865476f));
                    v1 = 0.5f * v1 * (1.f + erff(v1 * 0.7071067811865476f));
                }
                __half2 hh = __floats2half2_rn(v0, v1);
                *(__half2*)(C + (size_t)(rowBase + r) * Nc + gc) = hh;
            }
        } else {
            float* C = (float*)Cv;
            #pragma unroll 4
            for (int e = 0; e < 128; e++) {
                int r = e, c = tid;
                int gc = colBase + c;
                float v = smf[r * OSTR + c] + (bias ? bias[gc] : 0.f);
                C[(size_t)(rowBase + r) * Nc + gc] = v;
            }
        }
    } else {
        float* C = (float*)Cv;
        #pragma unroll 4
        for (int e = 0; e < 128; e++) {
            int r = e, c = tid;
            int gr = rowBase + r, gc = colBase + c;
            float v = smf[r * OSTR + c] + bias[gc];
            int orow = (epilogue == 2) ? map_row(gr, shifted) : gr;
            size_t off = (size_t)orow * Nc + gc;
            v += resid[off];
            C[off] = v;
            if (epilogue == 3) mirror[off] = __float2half(v);
        }
    }
}

// ---------------- weight fp32 -> fp16 ----------------
__global__ void tohalf_kernel(const float4* __restrict__ in, __half* __restrict__ out, int n4) {
    int i = blockIdx.x * blockDim.x + threadIdx.x;
    if (i < n4) {
        float4 v = in[i];
        __half2* o = (__half2*)(out + i * 4);
        o[0] = __floats2half2_rn(v.x, v.y);
        o[1] = __floats2half2_rn(v.z, v.w);
    }
}

// ---------------- LayerNorm over 384: 1 warp per row, 8 rows/block ----------------
__global__ __launch_bounds__(256)
void ln384_kernel(const float* __restrict__ src, __half* __restrict__ dst,
                  const float* __restrict__ g, const float* __restrict__ b,
                  int mode) {
    int row = blockIdx.x * 8 + (threadIdx.x >> 5);
    int lane = threadIdx.x & 31;
    int t = (mode == 0) ? row : map_row(row, mode == 2);
    const float* sp = src + (size_t)t * DIM;
    float v[12];
    float s = 0.f;
    #pragma unroll
    for (int e = 0; e < 12; e++) { v[e] = sp[lane + e * 32]; s += v[e]; }
    float m = warp_sum(s) * (1.f / 384.f);
    float vs = 0.f;
    #pragma unroll
    for (int e = 0; e < 12; e++) { v[e] -= m; vs += v[e] * v[e]; }
    float inv = rsqrtf(warp_sum(vs) * (1.f / 384.f) + 1e-5f);
    __half* dp = dst + (size_t)row * DIM;
    #pragma unroll
    for (int e = 0; e < 12; e++) {
        int c = lane + e * 32;
        dp[c] = __float2half(v[e] * inv * g[c] + b[c]);
    }
}

// ---------------- windowed attention: single-pass, 2 heads per 128-thread block ----
__global__ void attn_kernel(const __half* __restrict__ qkv, __half* __restrict__ o,
                            const float* __restrict__ rpb, int shifted) {
    __shared__ float4 ksm[2][49][8];
    __shared__ float4 vsm[2][49][8];
    int pair = blockIdx.x;
    int win  = pair / 6;
    int hp   = (pair % 6) * 2;
    int sub  = threadIdx.x >> 6;
    int t    = threadIdx.x & 63;
    int head = hp + sub;
    int wi = win & 63;
    int wh = wi >> 3, ww = wi & 7;
    int base = win * 49;

    for (int idx = t; idx < 49 * 8; idx += 64) {
        int j = idx >> 3, d4 = idx & 7;
        size_t ro = (size_t)(base + j) * QKVD + head * 32 + d4 * 4;
        const __half2* kp = (const __half2*)(qkv + ro + 384);
        const __half2* vp = (const __half2*)(qkv + ro + 768);
        float2 k0 = __half22float2(kp[0]), k1 = __half22float2(kp[1]);
        float2 w0 = __half22float2(vp[0]), w1 = __half22float2(vp[1]);
        ksm[sub][j][d4] = make_float4(k0.x, k0.y, k1.x, k1.y);
        vsm[sub][j][d4] = make_float4(w0.x, w0.y, w1.x, w1.y);
    }
    __syncthreads();

    if (t < 49) {
        int i = t, ri = i / 7, ci = i % 7;
        float4 q[8];
        const __half2* qp = (const __half2*)(qkv + (size_t)(base + i) * QKVD + head * 32);
        #pragma unroll
        for (int d4 = 0; d4 < 8; d4++) {
            float2 a = __half22float2(qp[d4 * 2]), b = __half22float2(qp[d4 * 2 + 1]);
            const float sc = 0.17677669529663687f;
            q[d4] = make_float4(a.x * sc, a.y * sc, b.x * sc, b.y * sc);
        }

        int lab_i = 0;
        if (shifted) {
            int hh = wh * 7 + ri, wc = ww * 7 + ci;
            int gh = hh < 49 ? 0 : (hh < 53 ? 1 : 2);
            int gw = wc < 49 ? 0 : (wc < 53 ? 1 : 2);
            lab_i = gh * 3 + gw;
        }

        float sum = 0.f;
        float4 accv[8];
        #pragma unroll
        for (int d4 = 0; d4 < 8; d4++) accv[d4] = make_float4(0.f, 0.f, 0.f, 0.f);

        for (int j = 0; j < 49; j++) {
            float s = 0.f;
            #pragma unroll
            for (int d4 = 0; d4 < 8; d4++) {
                float4 kv = ksm[sub][j][d4];
                s += q[d4].x * kv.x + q[d4].y * kv.y + q[d4].z * kv.z + q[d4].w * kv.w;
            }
            int rj = j / 7, cj = j % 7;
            int rpi = (ri - rj + 6) * 13 + (ci - cj + 6);
            s += rpb[rpi * 12 + head];
            if (shifted) {
                int hh = wh * 7 + rj, wc = ww * 7 + cj;
                int gh = hh < 49 ? 0 : (hh < 53 ? 1 : 2);
                int gw = wc < 49 ? 0 : (wc < 53 ? 1 : 2);
                if (gh * 3 + gw != lab_i) s -= 100.0f;
            }
            float e = expf(s);
            sum += e;
            #pragma unroll
            for (int d4 = 0; d4 < 8; d4++) {
                float4 vv = vsm[sub][j][d4];
                accv[d4].x += e * vv.x; accv[d4].y += e * vv.y;
                accv[d4].z += e * vv.z; accv[d4].w += e * vv.w;
            }
        }
        float inv = 1.0f / sum;
        __half2* op = (__half2*)(o + (size_t)(base + i) * DIM + head * 32);
        #pragma unroll
        for (int d4 = 0; d4 < 8; d4++) {
            op[d4 * 2]     = __floats2half2_rn(accv[d4].x * inv, accv[d4].y * inv);
            op[d4 * 2 + 1] = __floats2half2_rn(accv[d4].z * inv, accv[d4].w * inv);
        }
    }
}

// ---------------- PatchExpand pixel-shuffle + LN over 192: 1 warp per token ----------
__global__ __launch_bounds__(256)
void expand_ln_kernel(const float* __restrict__ e, float* __restrict__ out,
                      const float* __restrict__ g, const float* __restrict__ b) {
    int tt = blockIdx.x * 8 + (threadIdx.x >> 5);
    int lane = threadIdx.x & 31;
    int bb = tt / 12544;
    int rem = tt % 12544;
    int oh = rem / 112, ow = rem % 112;
    int h = oh >> 1, p = oh & 1, w = ow >> 1, q = ow & 1;
    int erow = bb * 3136 + h * 56 + w;
    const float* sp = e + (size_t)erow * EXPD + (p * 2 + q) * 192;
    float v[6];
    float s = 0.f;
    #pragma unroll
    for (int k = 0; k < 6; k++) { v[k] = sp[lane + k * 32]; s += v[k]; }
    float m = warp_sum(s) * (1.f / 192.f);
    float vs = 0.f;
    #pragma unroll
    for (int k = 0; k < 6; k++) { v[k] -= m; vs += v[k] * v[k]; }
    float inv = rsqrtf(warp_sum(vs) * (1.f / 192.f) + 1e-5f);
    float* dp = out + (size_t)tt * 192;
    #pragma unroll
    for (int k = 0; k < 6; k++) {
        int c = lane + k * 32;
        dp[c] = v[k] * inv * g[c] + b[c];
    }
}

// ---------------- host orchestration ----------------
extern "C" void kernel_launch(void* const* d_in, const int* in_sizes, int n_in,
                              void* d_out, int out_size) {
    const float* x    = (const float*)d_in[0];
    const float* n1g  = (const float*)d_in[1];
    const float* n1b  = (const float*)d_in[2];
    const float* qkvw = (const float*)d_in[3];
    const float* qkvb = (const float*)d_in[4];
    const float* rpb  = (const float*)d_in[5];
    const float* pw   = (const float*)d_in[6];
    const float* pb   = (const float*)d_in[7];
    const float* n2g  = (const float*)d_in[8];
    const float* n2b  = (const float*)d_in[9];
    const float* f1w  = (const float*)d_in[10];
    const float* f1b  = (const float*)d_in[11];
    const float* f2w  = (const float*)d_in[12];
    const float* f2b  = (const float*)d_in[13];
    const float* ew   = (const float*)d_in[14];
    const float* eg   = (const float*)d_in[15];
    const float* ebv  = (const float*)d_in[16];

    float *xb, *bigb;
    __half *xh, *yh, *oh, *wh;
    cudaGetSymbolAddress((void**)&xb,   g_x);
    cudaGetSymbolAddress((void**)&xh,   g_xh);
    cudaGetSymbolAddress((void**)&yh,   g_y);
    cudaGetSymbolAddress((void**)&oh,   g_o);
    cudaGetSymbolAddress((void**)&bigb, g_big);
    cudaGetSymbolAddress((void**)&wh,   g_w);

    static int smem_set = 0;
    const int GEMM_SMEM = 3 * STG * sizeof(__half);   // 107520 B
    if (!smem_set) {
        cudaFuncSetAttribute(gemm_fp16,
                             cudaFuncAttributeMaxDynamicSharedMemorySize, GEMM_SMEM);
        smem_set = 1;
    }

    tohalf_kernel<<<(884736/4 + 255)/256, 256>>>((const float4*)qkvw, wh + W_QKV, 884736/4);
    tohalf_kernel<<<(294912/4 + 255)/256, 256>>>((const float4*)pw,   wh + W_PROJ, 294912/4);
    tohalf_kernel<<<(1179648/4 + 255)/256, 256>>>((const float4*)f1w, wh + W_FC1, 1179648/4);
    tohalf_kernel<<<(1179648/4 + 255)/256, 256>>>((const float4*)f2w, wh + W_FC2, 1179648/4);
    tohalf_kernel<<<(294912/4 + 255)/256, 256>>>((const float4*)ew,   wh + W_EXP, 294912/4);

    const int MB = TOK / 128;
    for (int i = 0; i < 2; i++) {
        int sh = i;
        const float* res = (i == 0) ? x : xb;
        ln384_kernel<<<TOK / 8, 256>>>(res, yh, n1g + i * DIM, n1b + i * DIM, sh ? 2 : 1);
        gemm_fp16<<<dim3(QKVD / 128, MB), 128, GEMM_SMEM>>>(
            yh, wh + W_QKV + (size_t)i * DIM * QKVD, qkvb + i * QKVD,
            bigb, nullptr, nullptr, DIM, QKVD, 0, 0, 1);
        attn_kernel<<<1024 * 6, 128>>>((const __half*)bigb, oh, rpb + i * 169 * 12, sh);
        gemm_fp16<<<dim3(DIM / 128, MB), 128, GEMM_SMEM>>>(
            oh, wh + W_PROJ + (size_t)i * DIM * DIM, pb + i * DIM,
            xb, nullptr, res, DIM, DIM, 2, sh, 0);
        ln384_kernel<<<TOK / 8, 256>>>(xb, yh, n2g + i * DIM, n2b + i * DIM, 0);
        gemm_fp16<<<dim3(FFN / 128, MB), 128, GEMM_SMEM>>>(
            yh, wh + W_FC1 + (size_t)i * DIM * FFN, f1b + i * FFN,
            bigb, nullptr, nullptr, DIM, FFN, 1, 0, 1);
        gemm_fp16<<<dim3(DIM / 128, MB), 128, GEMM_SMEM>>>(
            (const __half*)bigb, wh + W_FC2 + (size_t)i * FFN * DIM, f2b + i * DIM,
            xb, xh, xb, FFN, DIM, 3, 0, 0);
    }

    gemm_fp16<<<dim3(EXPD / 128, MB), 128, GEMM_SMEM>>>(
        xh, wh + W_EXP, nullptr, bigb, nullptr, nullptr, DIM, EXPD, 0, 0, 0);
    expand_ln_kernel<<<TOK * 4 / 8, 256>>>(bigb, (float*)d_out, eg, ebv);
}

// round 10
// speedup vs baseline: 1.6257x; 1.0943x over previous
#include <cuda_runtime.h>
#include <cuda_fp16.h>
#include <math.h>
#include <stdint.h>
#include <mma.h>
using namespace nvcuda;

// ---------------- problem constants ----------------
#define TOK   50176
#define DIM   384
#define QKVD  1152
#define FFN   1536
#define EXPD  768

// ---------------- scratch ----------------
static __device__ float  g_x  [TOK * DIM];     // fp32 residual stream
static __device__ __half g_xh [TOK * DIM];     // fp16 mirror of final residual
static __device__ __half g_y  [TOK * DIM];     // LN outputs (fp16)
static __device__ __half g_o  [TOK * DIM];     // attention out (fp16)
static __device__ float  g_big[TOK * FFN];     // qkv/mid (as half) or expand out (float)
static __device__ __half g_w  [3833856];       // fp16 weights

#define W_QKV 0
#define W_PROJ 884736
#define W_FC1 1179648
#define W_FC2 2359296
#define W_EXP 3538944

// ---------------- helpers ----------------
__device__ __forceinline__ uint32_t smem_u32(const void* p) {
    uint32_t a;
    asm("{ .reg .u64 t; cvta.to.shared.u64 t, %1; cvt.u32.u64 %0, t; }" : "=r"(a) : "l"(p));
    return a;
}
__device__ __forceinline__ void cp16(uint32_t s, const void* g) {
    asm volatile("cp.async.cg.shared.global [%0], [%1], 16;" :: "r"(s), "l"(g) : "memory");
}
#define CP_COMMIT() asm volatile("cp.async.commit_group;" ::: "memory")
#define CP_WAIT(n)  asm volatile("cp.async.wait_group %0;" :: "n"(n) : "memory")

__device__ __forceinline__ int map_row(int ridx, int shifted) {
    int n  = ridx % 49;
    int wi = (ridx / 49) & 63;
    int b  = ridx / (49 * 64);
    int r = n / 7, c = n % 7;
    int wh = wi >> 3, ww = wi & 7;
    int h = wh * 7 + r, w = ww * 7 + c;
    if (shifted) { h = (h + 3) % 56; w = (w + 3) % 56; }
    return b * 3136 + h * 56 + w;
}

__device__ __forceinline__ float warp_sum(float v) {
    #pragma unroll
    for (int o = 16; o; o >>= 1) v += __shfl_xor_sync(0xffffffffu, v, o);
    return v;
}
__device__ __forceinline__ float gelu(float v) {
    return 0.5f * v * (1.f + erff(v * 0.7071067811865476f));
}

// ---------------- fp16 wmma GEMM: CTA 128x128, 4 warps of 64x64, BK=64 ----
// 3-stage cp.async pipeline, ONE barrier per k-iteration.
#define ASTR 72
#define BSTR 136
#define A_STAGE (128 * ASTR)
#define B_STAGE (64 * BSTR)
#define STG (A_STAGE + B_STAGE)         // 17920 halves = 35840 B / stage
#define OSTR 132

__global__ __launch_bounds__(128, 2)
void gemm_fp16(const __half* __restrict__ A, const __half* __restrict__ W,
               const float* __restrict__ bias, void* __restrict__ Cv,
               __half* __restrict__ mirror, const float* __restrict__ resid,
               int K, int Nc, int epilogue, int shifted, int out_half) {
    extern __shared__ __align__(16) char smraw[];
    __half* smh = (__half*)smraw;
    float*  smf = (float*)smraw;
    int tid = threadIdx.x;
    int wid = tid >> 5;
    int wm = (wid & 1) * 64;
    int wn = (wid >> 1) * 64;
    int rowBase = blockIdx.y * 128;
    int colBase = blockIdx.x * 128;
    int nk = K >> 6;

    wmma::fragment<wmma::accumulator, 16, 16, 16, float> acc[4][4];
    #pragma unroll
    for (int i = 0; i < 4; i++)
        #pragma unroll
        for (int j = 0; j < 4; j++) wmma::fill_fragment(acc[i][j], 0.f);

    #define STAGE_LOAD(kt, buf) do {                                              \
        __half* As_ = smh + (buf) * STG;                                          \
        __half* Bs_ = As_ + A_STAGE;                                              \
        uint32_t as_ = smem_u32(As_), bs_ = smem_u32(Bs_);                        \
        int kg_ = (kt) * 64;                                                      \
        _Pragma("unroll")                                                         \
        for (int l = 0; l < 8; l++) {                                             \
            int c = tid + l * 128;                                                \
            int r = c >> 3, q = (c & 7) * 8;                                      \
            cp16(as_ + (uint32_t)(r * ASTR + q) * 2,                              \
                 A + (size_t)(rowBase + r) * K + kg_ + q);                        \
            int kr = c >> 4, nq = (c & 15) * 8;                                   \
            cp16(bs_ + (uint32_t)(kr * BSTR + nq) * 2,                            \
                 W + (size_t)(kg_ + kr) * Nc + colBase + nq);                     \
        }                                                                         \
    } while (0)

    STAGE_LOAD(0, 0); CP_COMMIT();
    STAGE_LOAD(1, 1); CP_COMMIT();

    for (int kt = 0; kt < nk; kt++) {
        if (kt + 1 < nk) { CP_WAIT(1); } else { CP_WAIT(0); }
        __syncthreads();   // stage kt visible + all warps done with stage (kt-1)
        if (kt + 2 < nk) { STAGE_LOAD(kt + 2, (kt + 2) % 3); CP_COMMIT(); }

        const __half* As = smh + (kt % 3) * STG;
        const __half* Bs = As + A_STAGE;
        #pragma unroll
        for (int k16 = 0; k16 < 4; k16++) {
            wmma::fragment<wmma::matrix_a, 16, 16, 16, __half, wmma::row_major> af[4];
            wmma::fragment<wmma::matrix_b, 16, 16, 16, __half, wmma::row_major> bf[4];
            #pragma unroll
            for (int i = 0; i < 4; i++)
                wmma::load_matrix_sync(af[i], As + (wm + i * 16) * ASTR + k16 * 16, ASTR);
            #pragma unroll
            for (int j = 0; j < 4; j++)
                wmma::load_matrix_sync(bf[j], Bs + (k16 * 16) * BSTR + wn + j * 16, BSTR);
            #pragma unroll
            for (int i = 0; i < 4; i++)
                #pragma unroll
                for (int j = 0; j < 4; j++)
                    wmma::mma_sync(acc[i][j], af[i], bf[j], acc[i][j]);
        }
    }
    __syncthreads();   // all reads done before smem reuse as fp32 stage

    #pragma unroll
    for (int i = 0; i < 4; i++)
        #pragma unroll
        for (int j = 0; j < 4; j++)
            wmma::store_matrix_sync(smf + (wm + i * 16) * OSTR + wn + j * 16,
                                    acc[i][j], OSTR, wmma::mem_row_major);
    __syncthreads();

    if (epilogue <= 1) {
        if (out_half) {
            __half* C = (__half*)Cv;
            #pragma unroll 4
            for (int e = 0; e < 32; e++) {
                int idx = tid + e * 128;
                int r = idx >> 5, c4 = (idx & 31) * 4;
                int gc = colBase + c4;
                float4 v = *(const float4*)(smf + r * OSTR + c4);
                if (bias) {
                    float4 bv = *(const float4*)(bias + gc);
                    v.x += bv.x; v.y += bv.y; v.z += bv.z; v.w += bv.w;
                }
                if (epilogue == 1) {
                    v.x = gelu(v.x); v.y = gelu(v.y); v.z = gelu(v.z); v.w = gelu(v.w);
                }
                __half2 h0 = __floats2half2_rn(v.x, v.y);
                __half2 h1 = __floats2half2_rn(v.z, v.w);
                __half2* cp = (__half2*)(C + (size_t)(rowBase + r) * Nc + gc);
                cp[0] = h0; cp[1] = h1;
            }
        } else {
            float* C = (float*)Cv;
            #pragma unroll 4
            for (int e = 0; e < 32; e++) {
                int idx = tid + e * 128;
                int r = idx >> 5, c4 = (idx & 31) * 4;
                int gc = colBase + c4;
                float4 v = *(const float4*)(smf + r * OSTR + c4);
                if (bias) {
                    float4 bv = *(const float4*)(bias + gc);
                    v.x += bv.x; v.y += bv.y; v.z += bv.z; v.w += bv.w;
                }
                *(float4*)(C + (size_t)(rowBase + r) * Nc + gc) = v;
            }
        }
    } else {
        float* C = (float*)Cv;
        #pragma unroll 4
        for (int e = 0; e < 32; e++) {
            int idx = tid + e * 128;
            int r = idx >> 5, c4 = (idx & 31) * 4;
            int gr = rowBase + r, gc = colBase + c4;
            float4 v = *(const float4*)(smf + r * OSTR + c4);
            float4 bv = *(const float4*)(bias + gc);
            v.x += bv.x; v.y += bv.y; v.z += bv.z; v.w += bv.w;
            int orow = (epilogue == 2) ? map_row(gr, shifted) : gr;
            size_t off = (size_t)orow * Nc + gc;
            float4 rv = *(const float4*)(resid + off);
            v.x += rv.x; v.y += rv.y; v.z += rv.z; v.w += rv.w;
            *(float4*)(C + off) = v;
            if (epilogue == 3) {
                __half2* mp = (__half2*)(mirror + off);
                mp[0] = __floats2half2_rn(v.x, v.y);
                mp[1] = __floats2half2_rn(v.z, v.w);
            }
        }
    }
}

// ---------------- weight fp32 -> fp16 ----------------
__global__ void tohalf_kernel(const float4* __restrict__ in, __half* __restrict__ out, int n4) {
    int i = blockIdx.x * blockDim.x + threadIdx.x;
    if (i < n4) {
        float4 v = in[i];
        __half2* o = (__half2*)(out + i * 4);
        o[0] = __floats2half2_rn(v.x, v.y);
        o[1] = __floats2half2_rn(v.z, v.w);
    }
}

// ---------------- LayerNorm over 384: 1 warp per row, 8 rows/block ----------------
__global__ __launch_bounds__(256)
void ln384_kernel(const float* __restrict__ src, __half* __restrict__ dst,
                  const float* __restrict__ g, const float* __restrict__ b,
                  int mode) {
    int row = blockIdx.x * 8 + (threadIdx.x >> 5);
    int lane = threadIdx.x & 31;
    int t = (mode == 0) ? row : map_row(row, mode == 2);
    const float* sp = src + (size_t)t * DIM;
    float v[12];
    float s = 0.f;
    #pragma unroll
    for (int e = 0; e < 12; e++) { v[e] = sp[lane + e * 32]; s += v[e]; }
    float m = warp_sum(s) * (1.f / 384.f);
    float vs = 0.f;
    #pragma unroll
    for (int e = 0; e < 12; e++) { v[e] -= m; vs += v[e] * v[e]; }
    float inv = rsqrtf(warp_sum(vs) * (1.f / 384.f) + 1e-5f);
    __half* dp = dst + (size_t)row * DIM;
    #pragma unroll
    for (int e = 0; e < 12; e++) {
        int c = lane + e * 32;
        dp[c] = __float2half(v[e] * inv * g[c] + b[c]);
    }
}

// ---------------- windowed attention: single-pass, 2 heads per 128-thread block ----
__global__ void attn_kernel(const __half* __restrict__ qkv, __half* __restrict__ o,
                            const float* __restrict__ rpb, int shifted) {
    __shared__ float4 ksm[2][49][8];
    __shared__ float4 vsm[2][49][8];
    int pair = blockIdx.x;
    int win  = pair / 6;
    int hp   = (pair % 6) * 2;
    int sub  = threadIdx.x >> 6;
    int t    = threadIdx.x & 63;
    int head = hp + sub;
    int wi = win & 63;
    int wh = wi >> 3, ww = wi & 7;
    int base = win * 49;

    for (int idx = t; idx < 49 * 8; idx += 64) {
        int j = idx >> 3, d4 = idx & 7;
        size_t ro = (size_t)(base + j) * QKVD + head * 32 + d4 * 4;
        const __half2* kp = (const __half2*)(qkv + ro + 384);
        const __half2* vp = (const __half2*)(qkv + ro + 768);
        float2 k0 = __half22float2(kp[0]), k1 = __half22float2(kp[1]);
        float2 w0 = __half22float2(vp[0]), w1 = __half22float2(vp[1]);
        ksm[sub][j][d4] = make_float4(k0.x, k0.y, k1.x, k1.y);
        vsm[sub][j][d4] = make_float4(w0.x, w0.y, w1.x, w1.y);
    }
    __syncthreads();

    if (t < 49) {
        int i = t, ri = i / 7, ci = i % 7;
        float4 q[8];
        const __half2* qp = (const __half2*)(qkv + (size_t)(base + i) * QKVD + head * 32);
        #pragma unroll
        for (int d4 = 0; d4 < 8; d4++) {
            float2 a = __half22float2(qp[d4 * 2]), b = __half22float2(qp[d4 * 2 + 1]);
            const float sc = 0.17677669529663687f;
            q[d4] = make_float4(a.x * sc, a.y * sc, b.x * sc, b.y * sc);
        }

        int lab_i = 0;
        if (shifted) {
            int hh = wh * 7 + ri, wc = ww * 7 + ci;
            int gh = hh < 49 ? 0 : (hh < 53 ? 1 : 2);
            int gw = wc < 49 ? 0 : (wc < 53 ? 1 : 2);
            lab_i = gh * 3 + gw;
        }

        float sum = 0.f;
        float4 accv[8];
        #pragma unroll
        for (int d4 = 0; d4 < 8; d4++) accv[d4] = make_float4(0.f, 0.f, 0.f, 0.f);

        for (int j = 0; j < 49; j++) {
            float s = 0.f;
            #pragma unroll
            for (int d4 = 0; d4 < 8; d4++) {
                float4 kv = ksm[sub][j][d4];
                s += q[d4].x * kv.x + q[d4].y * kv.y + q[d4].z * kv.z + q[d4].w * kv.w;
            }
            int rj = j / 7, cj = j % 7;
            int rpi = (ri - rj + 6) * 13 + (ci - cj + 6);
            s += rpb[rpi * 12 + head];
            if (shifted) {
                int hh = wh * 7 + rj, wc = ww * 7 + cj;
                int gh = hh < 49 ? 0 : (hh < 53 ? 1 : 2);
                int gw = wc < 49 ? 0 : (wc < 53 ? 1 : 2);
                if (gh * 3 + gw != lab_i) s -= 100.0f;
            }
            float e = expf(s);
            sum += e;
            #pragma unroll
            for (int d4 = 0; d4 < 8; d4++) {
                float4 vv = vsm[sub][j][d4];
                accv[d4].x += e * vv.x; accv[d4].y += e * vv.y;
                accv[d4].z += e * vv.z; accv[d4].w += e * vv.w;
            }
        }
        float inv = 1.0f / sum;
        __half2* op = (__half2*)(o + (size_t)(base + i) * DIM + head * 32);
        #pragma unroll
        for (int d4 = 0; d4 < 8; d4++) {
            op[d4 * 2]     = __floats2half2_rn(accv[d4].x * inv, accv[d4].y * inv);
            op[d4 * 2 + 1] = __floats2half2_rn(accv[d4].z * inv, accv[d4].w * inv);
        }
    }
}

// ---------------- PatchExpand pixel-shuffle + LN over 192: 1 warp per token ----------
__global__ __launch_bounds__(256)
void expand_ln_kernel(const float* __restrict__ e, float* __restrict__ out,
                      const float* __restrict__ g, const float* __restrict__ b) {
    int tt = blockIdx.x * 8 + (threadIdx.x >> 5);
    int lane = threadIdx.x & 31;
    int bb = tt / 12544;
    int rem = tt % 12544;
    int oh = rem / 112, ow = rem % 112;
    int h = oh >> 1, p = oh & 1, w = ow >> 1, q = ow & 1;
    int erow = bb * 3136 + h * 56 + w;
    const float* sp = e + (size_t)erow * EXPD + (p * 2 + q) * 192;
    float v[6];
    float s = 0.f;
    #pragma unroll
    for (int k = 0; k < 6; k++) { v[k] = sp[lane + k * 32]; s += v[k]; }
    float m = warp_sum(s) * (1.f / 192.f);
    float vs = 0.f;
    #pragma unroll
    for (int k = 0; k < 6; k++) { v[k] -= m; vs += v[k] * v[k]; }
    float inv = rsqrtf(warp_sum(vs) * (1.f / 192.f) + 1e-5f);
    float* dp = out + (size_t)tt * 192;
    #pragma unroll
    for (int k = 0; k < 6; k++) {
        int c = lane + k * 32;
        dp[c] = v[k] * inv * g[c] + b[c];
    }
}

// ---------------- host orchestration ----------------
extern "C" void kernel_launch(void* const* d_in, const int* in_sizes, int n_in,
                              void* d_out, int out_size) {
    const float* x    = (const float*)d_in[0];
    const float* n1g  = (const float*)d_in[1];
    const float* n1b  = (const float*)d_in[2];
    const float* qkvw = (const float*)d_in[3];
    const float* qkvb = (const float*)d_in[4];
    const float* rpb  = (const float*)d_in[5];
    const float* pw   = (const float*)d_in[6];
    const float* pb   = (const float*)d_in[7];
    const float* n2g  = (const float*)d_in[8];
    const float* n2b  = (const float*)d_in[9];
    const float* f1w  = (const float*)d_in[10];
    const float* f1b  = (const float*)d_in[11];
    const float* f2w  = (const float*)d_in[12];
    const float* f2b  = (const float*)d_in[13];
    const float* ew   = (const float*)d_in[14];
    const float* eg   = (const float*)d_in[15];
    const float* ebv  = (const float*)d_in[16];

    float *xb, *bigb;
    __half *xh, *yh, *oh, *wh;
    cudaGetSymbolAddress((void**)&xb,   g_x);
    cudaGetSymbolAddress((void**)&xh,   g_xh);
    cudaGetSymbolAddress((void**)&yh,   g_y);
    cudaGetSymbolAddress((void**)&oh,   g_o);
    cudaGetSymbolAddress((void**)&bigb, g_big);
    cudaGetSymbolAddress((void**)&wh,   g_w);

    static int smem_set = 0;
    const int GEMM_SMEM = 3 * STG * sizeof(__half);   // 107520 B
    if (!smem_set) {
        cudaFuncSetAttribute(gemm_fp16,
                             cudaFuncAttributeMaxDynamicSharedMemorySize, GEMM_SMEM);
        smem_set = 1;
    }

    tohalf_kernel<<<(884736/4 + 255)/256, 256>>>((const float4*)qkvw, wh + W_QKV, 884736/4);
    tohalf_kernel<<<(294912/4 + 255)/256, 256>>>((const float4*)pw,   wh + W_PROJ, 294912/4);
    tohalf_kernel<<<(1179648/4 + 255)/256, 256>>>((const float4*)f1w, wh + W_FC1, 1179648/4);
    tohalf_kernel<<<(1179648/4 + 255)/256, 256>>>((const float4*)f2w, wh + W_FC2, 1179648/4);
    tohalf_kernel<<<(294912/4 + 255)/256, 256>>>((const float4*)ew,   wh + W_EXP, 294912/4);

    const int MB = TOK / 128;
    for (int i = 0; i < 2; i++) {
        int sh = i;
        const float* res = (i == 0) ? x : xb;
        ln384_kernel<<<TOK / 8, 256>>>(res, yh, n1g + i * DIM, n1b + i * DIM, sh ? 2 : 1);
        gemm_fp16<<<dim3(QKVD / 128, MB), 128, GEMM_SMEM>>>(
            yh, wh + W_QKV + (size_t)i * DIM * QKVD, qkvb + i * QKVD,
            bigb, nullptr, nullptr, DIM, QKVD, 0, 0, 1);
        attn_kernel<<<1024 * 6, 128>>>((const __half*)bigb, oh, rpb + i * 169 * 12, sh);
        gemm_fp16<<<dim3(DIM / 128, MB), 128, GEMM_SMEM>>>(
            oh, wh + W_PROJ + (size_t)i * DIM * DIM, pb + i * DIM,
            xb, nullptr, res, DIM, DIM, 2, sh, 0);
        ln384_kernel<<<TOK / 8, 256>>>(xb, yh, n2g + i * DIM, n2b + i * DIM, 0);
        gemm_fp16<<<dim3(FFN / 128, MB), 128, GEMM_SMEM>>>(
            yh, wh + W_FC1 + (size_t)i * DIM * FFN, f1b + i * FFN,
            bigb, nullptr, nullptr, DIM, FFN, 1, 0, 1);
        gemm_fp16<<<dim3(DIM / 128, MB), 128, GEMM_SMEM>>>(
            (const __half*)bigb, wh + W_FC2 + (size_t)i * FFN * DIM, f2b + i * DIM,
            xb, xh, xb, FFN, DIM, 3, 0, 0);
    }

    gemm_fp16<<<dim3(EXPD / 128, MB), 128, GEMM_SMEM>>>(
        xh, wh + W_EXP, nullptr, bigb, nullptr, nullptr, DIM, EXPD, 0, 0, 0);
    expand_ln_kernel<<<TOK * 4 / 8, 256>>>(bigb, (float*)d_out, eg, ebv);
}